// round 8
// baseline (speedup 1.0000x reference)
#include <cuda_runtime.h>
#include <cuda_fp16.h>
#include <cstdint>
#include <math.h>

#define TOK 8192
#define DIM 2048
#define DHID 1024
#define DOUT 1024

// ---------------------------------------------------------------------------
// Scratch (__device__ globals; allocation-free per harness rules)
// ---------------------------------------------------------------------------
__device__ __align__(256) float g_s[(size_t)TOK * TOK];             // fp32 scores

__device__ __align__(256) __half g_O0h[(size_t)TOK * DIM];
__device__ __align__(256) __half g_O0l[(size_t)TOK * DIM];
__device__ __align__(256) __half g_Wwh[(size_t)DHID * DIM];
__device__ __align__(256) __half g_Wwl[(size_t)DHID * DIM];
__device__ __align__(256) __half g_Uwh[(size_t)DHID * DIM];
__device__ __align__(256) __half g_Uwl[(size_t)DHID * DIM];
__device__ __align__(256) __half g_Hwh[(size_t)DHID * DIM];
__device__ __align__(256) __half g_Hwl[(size_t)DHID * DIM];
__device__ __align__(256) __half g_qh[(size_t)TOK * DHID];
__device__ __align__(256) __half g_ql[(size_t)TOK * DHID];
__device__ __align__(256) __half g_kh[(size_t)TOK * DHID];
__device__ __align__(256) __half g_kl[(size_t)TOK * DHID];
__device__ __align__(256) __half g_vTh[(size_t)DHID * TOK];
__device__ __align__(256) __half g_vTl[(size_t)DHID * TOK];
__device__ __align__(256) __half g_Sh[(size_t)TOK * TOK];
__device__ __align__(256) __half g_Sl[(size_t)TOK * TOK];
__device__ __align__(256) __half g_ch[(size_t)TOK * DHID];
__device__ __align__(256) __half g_cl[(size_t)TOK * DHID];
__device__ __align__(256) __half g_f0h[(size_t)DIM * DHID];
__device__ __align__(256) __half g_f0l[(size_t)DIM * DHID];
__device__ __align__(256) __half g_O1h[(size_t)TOK * DIM];
__device__ __align__(256) __half g_O1l[(size_t)TOK * DIM];
__device__ __align__(256) __half g_f1h[(size_t)DOUT * DIM];
__device__ __align__(256) __half g_f1l[(size_t)DOUT * DIM];

// ---------------------------------------------------------------------------
// helpers
// ---------------------------------------------------------------------------
__device__ __forceinline__ uint32_t smem_to_u32(const void* p) {
    uint32_t a;
    asm("{ .reg .u64 t; cvta.to.shared.u64 t, %1; cvt.u32.u64 %0, t; }" : "=r"(a) : "l"(p));
    return a;
}
#define SWZ128(o) ((o) ^ (((o) >> 3) & 0x70))

__device__ __forceinline__ void ldmatrix4(uint32_t* r, uint32_t addr) {
    asm volatile("ldmatrix.sync.aligned.m8n8.x4.shared.b16 {%0,%1,%2,%3}, [%4];"
                 : "=r"(r[0]), "=r"(r[1]), "=r"(r[2]), "=r"(r[3]) : "r"(addr));
}
__device__ __forceinline__ void mma16816(float* c, const uint32_t* a, const uint32_t* b) {
    asm volatile("mma.sync.aligned.m16n8k16.row.col.f32.f16.f16.f32 "
                 "{%0,%1,%2,%3}, {%4,%5,%6,%7}, {%8,%9}, {%0,%1,%2,%3};"
                 : "+f"(c[0]), "+f"(c[1]), "+f"(c[2]), "+f"(c[3])
                 : "r"(a[0]), "r"(a[1]), "r"(a[2]), "r"(a[3]), "r"(b[0]), "r"(b[1]));
}
__device__ __forceinline__ void cp_async16(uint32_t dst, const void* src) {
    asm volatile("cp.async.cg.shared.global [%0], [%1], 16;" :: "r"(dst), "l"(src));
}
#define CP_COMMIT()  asm volatile("cp.async.commit_group;" ::: "memory")
#define CP_WAIT1()   asm volatile("cp.async.wait_group 1;" ::: "memory")

__device__ __forceinline__ void pair_store(__half* __restrict__ hi,
                                           __half* __restrict__ lo,
                                           size_t idx, float v) {
    __half h = __float2half_rn(v);
    hi[idx] = h;
    lo[idx] = __float2half_rn(v - __half2float(h));
}

// ---------------------------------------------------------------------------
// Persistent GEMM NT: C[M,N] = pair(A)[M,K] * pair(B)[N,K]^T (+bias)(+res)
// CTA tile 128x256, BK=32, SW128 smem [hi 64B | lo 64B] per row.
// 8 warps 2(m) x 4(n), warp tile 64x64.
// SWEEPS=3: hi*hi + lo(A)*hi(B) + hi(A)*lo(B);  SWEEPS=2: drops B-lo term.
// 3-stage cp.async pipeline. Each CTA loops over tiles (persistent).
// ---------------------------------------------------------------------------
#define STAGE_BYTES 49152
#define SM_BYTES (3 * STAGE_BYTES)

template<int SWEEPS, bool COLBIAS, bool ROWBIAS, bool RES, bool OUTF, bool OUTP>
__global__ void __launch_bounds__(256, 1)
gemm_pair(const __half* __restrict__ Ahi, const __half* __restrict__ Alo,
          const __half* __restrict__ Bhi, const __half* __restrict__ Blo,
          const float* __restrict__ bias, const float* __restrict__ res,
          float* __restrict__ Cf,
          __half* __restrict__ Chi, __half* __restrict__ Clo,
          int gx, int ntiles, int N, int K)
{
    extern __shared__ char smem[];
    const uint32_t smem_base = smem_to_u32(smem);
    const int tid  = threadIdx.x;
    const int wid  = tid >> 5;
    const int lane = tid & 31;
    const int wm   = wid >> 2;        // 0..1  (m 64-row half)
    const int wn   = wid & 3;         // 0..3  (n 64-col quarter)

    const int NCH = K >> 5;           // K/32 chunks

    // ldmatrix address components (constant across chunks/tiles)
    const int arow0 = (wm << 6) + (lane & 15);
    const uint32_t acol = (uint32_t)((lane >> 4) << 4);
    const int brow0 = (wn << 6) + ((lane >> 4) << 3) + (lane & 7);
    const uint32_t bcol = (uint32_t)(((lane >> 3) & 1) << 4);

    for (int t = blockIdx.x; t < ntiles; t += gridDim.x) {
        const int bm = (t / gx) << 7;
        const int bn = (t % gx) << 8;

        __syncthreads();   // prior tile's smem readers done before refill

        float acc[4][8][4];
        #pragma unroll
        for (int i = 0; i < 4; i++)
            #pragma unroll
            for (int j = 0; j < 8; j++)
                #pragma unroll
                for (int e = 0; e < 4; e++) acc[i][j][e] = 0.0f;

        // stage layout: A 128 rows x 128B at +0 (16KB), B 256 rows x 128B at +16KB
        auto load_chunk = [&](int kk, int slot) {
            const uint32_t sbase = smem_base + slot * STAGE_BYTES;
            #pragma unroll
            for (int it = 0; it < 12; it++) {
                int id  = it * 256 + tid;         // 0..3071 16B-chunks
                int isB = id >= 1024;
                int id2 = isB ? id - 1024 : id;
                int row = id2 >> 3;
                int rem = id2 & 7;
                int hl  = rem >> 2;               // 0 = hi, 1 = lo
                int kc  = rem & 3;                // 16B piece within 64B half
                uint32_t cb  = (uint32_t)(hl * 64 + kc * 16);
                uint32_t dst = sbase + (isB ? 16384u : 0u)
                             + SWZ128((uint32_t)(row << 7) + cb);
                const __half* src;
                if (isB) src = (hl ? Blo : Bhi) + (size_t)(bn + row) * K;
                else     src = (hl ? Alo : Ahi) + (size_t)(bm + row) * K;
                cp_async16(dst, src + ((size_t)kk << 5) + kc * 8);
            }
        };

        load_chunk(0, 0); CP_COMMIT();
        load_chunk(1, 1); CP_COMMIT();

        for (int c = 0; c < NCH; c++) {
            CP_WAIT1();
            __syncthreads();
            const uint32_t sbase = smem_base + (c % 3) * STAGE_BYTES;
            const uint32_t Abase = sbase;
            const uint32_t Bbase = sbase + 16384u;

            #pragma unroll
            for (int ks = 0; ks < 2; ks++) {
                const uint32_t kb = (uint32_t)(ks << 5);
                uint32_t Ah[4][4], Ax[4][4], Bf[4][4];
                #pragma unroll
                for (int f = 0; f < 4; f++) {
                    uint32_t ro = (uint32_t)((arow0 + (f << 4)) << 7);
                    ldmatrix4(Ah[f], Abase + SWZ128(ro + kb + acol));
                }
                #pragma unroll
                for (int g = 0; g < 4; g++) {
                    uint32_t ro = (uint32_t)((brow0 + (g << 4)) << 7);
                    ldmatrix4(Bf[g], Bbase + SWZ128(ro + kb + bcol));
                }
                // hi * hi
                #pragma unroll
                for (int mf = 0; mf < 4; mf++)
                    #pragma unroll
                    for (int nf = 0; nf < 8; nf++)
                        mma16816(acc[mf][nf], Ah[mf], &Bf[nf >> 1][(nf & 1) << 1]);
                // lo(A) * hi(B)
                #pragma unroll
                for (int f = 0; f < 4; f++) {
                    uint32_t ro = (uint32_t)((arow0 + (f << 4)) << 7);
                    ldmatrix4(Ax[f], Abase + SWZ128(ro + kb + acol + 64u));
                }
                #pragma unroll
                for (int mf = 0; mf < 4; mf++)
                    #pragma unroll
                    for (int nf = 0; nf < 8; nf++)
                        mma16816(acc[mf][nf], Ax[mf], &Bf[nf >> 1][(nf & 1) << 1]);
                if (SWEEPS == 3) {
                    // hi(A) * lo(B)
                    #pragma unroll
                    for (int g = 0; g < 4; g++) {
                        uint32_t ro = (uint32_t)((brow0 + (g << 4)) << 7);
                        ldmatrix4(Bf[g], Bbase + SWZ128(ro + kb + bcol + 64u));
                    }
                    #pragma unroll
                    for (int mf = 0; mf < 4; mf++)
                        #pragma unroll
                        for (int nf = 0; nf < 8; nf++)
                            mma16816(acc[mf][nf], Ah[mf], &Bf[nf >> 1][(nf & 1) << 1]);
                }
            }
            if (c + 2 < NCH) load_chunk(c + 2, (c + 2) % 3);
            CP_COMMIT();
        }

        // ------------------------- epilogue -------------------------
        const int qrow = lane >> 2;
        const int qcol = (lane & 3) << 1;
        #pragma unroll
        for (int mf = 0; mf < 4; mf++) {
            #pragma unroll
            for (int half = 0; half < 2; half++) {
                const int r = bm + (wm << 6) + (mf << 4) + qrow + (half << 3);
                float rb = 0.0f;
                if (ROWBIAS) rb = bias[r];
                #pragma unroll
                for (int nf = 0; nf < 8; nf++) {
                    const int col = bn + (wn << 6) + (nf << 3) + qcol;
                    const size_t idx = (size_t)r * N + col;
                    float v0 = acc[mf][nf][half * 2 + 0];
                    float v1 = acc[mf][nf][half * 2 + 1];
                    if (COLBIAS) { v0 += bias[col]; v1 += bias[col + 1]; }
                    if (ROWBIAS) { v0 += rb; v1 += rb; }
                    if (RES)     { v0 += res[idx]; v1 += res[idx + 1]; }
                    if (OUTF)    { *(float2*)(Cf + idx) = make_float2(v0, v1); }
                    if (OUTP) {
                        pair_store(Chi, Clo, idx,     v0);
                        pair_store(Chi, Clo, idx + 1, v1);
                    }
                }
            }
        }
    }
}

// ---------------------------------------------------------------------------
// Fused fp32 -> (hi, lo) fp16 split conversion for all 6 source arrays
// segment sizes in float4: O0 = 4194304, then 5 x 524288
// ---------------------------------------------------------------------------
#define SEG0 4194304
#define SEGW 524288

__global__ void __launch_bounds__(256)
pairify_all(const float4* __restrict__ O0,   __half* __restrict__ O0h,  __half* __restrict__ O0l,
            const float4* __restrict__ Ww,   __half* __restrict__ Wwh,  __half* __restrict__ Wwl,
            const float4* __restrict__ Uw,   __half* __restrict__ Uwh,  __half* __restrict__ Uwl,
            const float4* __restrict__ Hw,   __half* __restrict__ Hwh,  __half* __restrict__ Hwl,
            const float4* __restrict__ f0w,  __half* __restrict__ f0h,  __half* __restrict__ f0l,
            const float4* __restrict__ f1w,  __half* __restrict__ f1h,  __half* __restrict__ f1l)
{
    int i = blockIdx.x * blockDim.x + threadIdx.x;
    const float4* src; __half* hi; __half* lo; int off;
    if (i < SEG0) {
        src = O0; hi = O0h; lo = O0l; off = i;
    } else {
        int j = i - SEG0;
        int seg = j / SEGW;
        off = j - seg * SEGW;
        switch (seg) {
            case 0:  src = Ww;  hi = Wwh; lo = Wwl; break;
            case 1:  src = Uw;  hi = Uwh; lo = Uwl; break;
            case 2:  src = Hw;  hi = Hwh; lo = Hwl; break;
            case 3:  src = f0w; hi = f0h; lo = f0l; break;
            default: src = f1w; hi = f1h; lo = f1l; break;
        }
    }
    float4 v = src[off];
    size_t b = (size_t)off * 4;
    pair_store(hi, lo, b + 0, v.x);
    pair_store(hi, lo, b + 1, v.y);
    pair_store(hi, lo, b + 2, v.z);
    pair_store(hi, lo, b + 3, v.w);
}

// ---------------------------------------------------------------------------
// Row softmax: fp32 scores in, (hi, lo) fp16 split weights out
// ---------------------------------------------------------------------------
__global__ void __launch_bounds__(256)
softmax_pair(const float* __restrict__ S, __half* __restrict__ Wh,
             __half* __restrict__ Wl)
{
    __shared__ float red[8];
    const size_t rowbase = (size_t)blockIdx.x * TOK;
    const float* p = S + rowbase;
    const int tid = threadIdx.x;
    const int lane = tid & 31;
    const int warp = tid >> 5;

    float4 vals[8];
    float lmax = -INFINITY;
    #pragma unroll
    for (int i = 0; i < 8; i++) {
        vals[i] = *(const float4*)(p + ((i << 8) + tid) * 4);
        lmax = fmaxf(lmax, fmaxf(fmaxf(vals[i].x, vals[i].y), fmaxf(vals[i].z, vals[i].w)));
    }
    #pragma unroll
    for (int o = 16; o > 0; o >>= 1)
        lmax = fmaxf(lmax, __shfl_xor_sync(0xffffffffu, lmax, o));
    if (lane == 0) red[warp] = lmax;
    __syncthreads();
    float rmax = red[0];
    #pragma unroll
    for (int w = 1; w < 8; w++) rmax = fmaxf(rmax, red[w]);
    __syncthreads();

    float lsum = 0.0f;
    #pragma unroll
    for (int i = 0; i < 8; i++) {
        vals[i].x = expf(vals[i].x - rmax);
        vals[i].y = expf(vals[i].y - rmax);
        vals[i].z = expf(vals[i].z - rmax);
        vals[i].w = expf(vals[i].w - rmax);
        lsum += (vals[i].x + vals[i].y) + (vals[i].z + vals[i].w);
    }
    #pragma unroll
    for (int o = 16; o > 0; o >>= 1)
        lsum += __shfl_xor_sync(0xffffffffu, lsum, o);
    if (lane == 0) red[warp] = lsum;
    __syncthreads();
    float rsum = 0.0f;
    #pragma unroll
    for (int w = 0; w < 8; w++) rsum += red[w];
    const float inv = 1.0f / rsum;

    #pragma unroll
    for (int i = 0; i < 8; i++) {
        const size_t b = rowbase + ((i << 8) + tid) * 4;
        pair_store(Wh, Wl, b + 0, vals[i].x * inv);
        pair_store(Wh, Wl, b + 1, vals[i].y * inv);
        pair_store(Wh, Wl, b + 2, vals[i].z * inv);
        pair_store(Wh, Wl, b + 3, vals[i].w * inv);
    }
}

// ---------------------------------------------------------------------------
// Launch
// ---------------------------------------------------------------------------
template<int SW, bool CB, bool RB, bool RE, bool OF, bool OP>
static void set_smem_attr() {
    cudaFuncSetAttribute(gemm_pair<SW, CB, RB, RE, OF, OP>,
                         cudaFuncAttributeMaxDynamicSharedMemorySize, SM_BYTES);
}

extern "C" void kernel_launch(void* const* d_in, const int* in_sizes, int n_in,
                              void* d_out, int out_size)
{
    const float* O0   = (const float*)d_in[0];
    const float* Ww   = (const float*)d_in[1];
    const float* Wb   = (const float*)d_in[2];
    const float* Uw   = (const float*)d_in[3];
    const float* Ub   = (const float*)d_in[4];
    const float* Hw   = (const float*)d_in[5];
    const float* Hb   = (const float*)d_in[6];
    const float* fc0w = (const float*)d_in[7];
    const float* fc0b = (const float*)d_in[8];
    const float* fc1w = (const float*)d_in[9];
    const float* fc1b = (const float*)d_in[10];

    float* O1 = (float*)d_out;
    float* O2 = O1 + (size_t)TOK * DIM;

    set_smem_attr<3, true,  false, false, false, true >();  // q, k
    set_smem_attr<3, false, true,  false, false, true >();  // vT
    set_smem_attr<3, false, false, false, true,  false>();  // scores
    set_smem_attr<2, false, false, false, false, true >();  // ctx
    set_smem_attr<2, true,  false, true,  true,  true >();  // fc0
    set_smem_attr<2, true,  false, false, true,  false>();  // fc1

    int nsm = 148;
    cudaDeviceGetAttribute(&nsm, cudaDevAttrMultiProcessorCount, 0);

    float* s;
    __half *O0h, *O0l, *Wwh, *Wwl, *Uwh, *Uwl, *Hwh, *Hwl;
    __half *qh, *ql, *kh, *kl, *vTh, *vTl, *Sh, *Sl, *ch, *cl;
    __half *f0h, *f0l, *O1h, *O1l, *f1h, *f1l;
    cudaGetSymbolAddress((void**)&s,   g_s);
    cudaGetSymbolAddress((void**)&O0h, g_O0h); cudaGetSymbolAddress((void**)&O0l, g_O0l);
    cudaGetSymbolAddress((void**)&Wwh, g_Wwh); cudaGetSymbolAddress((void**)&Wwl, g_Wwl);
    cudaGetSymbolAddress((void**)&Uwh, g_Uwh); cudaGetSymbolAddress((void**)&Uwl, g_Uwl);
    cudaGetSymbolAddress((void**)&Hwh, g_Hwh); cudaGetSymbolAddress((void**)&Hwl, g_Hwl);
    cudaGetSymbolAddress((void**)&qh,  g_qh);  cudaGetSymbolAddress((void**)&ql,  g_ql);
    cudaGetSymbolAddress((void**)&kh,  g_kh);  cudaGetSymbolAddress((void**)&kl,  g_kl);
    cudaGetSymbolAddress((void**)&vTh, g_vTh); cudaGetSymbolAddress((void**)&vTl, g_vTl);
    cudaGetSymbolAddress((void**)&Sh,  g_Sh);  cudaGetSymbolAddress((void**)&Sl,  g_Sl);
    cudaGetSymbolAddress((void**)&ch,  g_ch);  cudaGetSymbolAddress((void**)&cl,  g_cl);
    cudaGetSymbolAddress((void**)&f0h, g_f0h); cudaGetSymbolAddress((void**)&f0l, g_f0l);
    cudaGetSymbolAddress((void**)&O1h, g_O1h); cudaGetSymbolAddress((void**)&O1l, g_O1l);
    cudaGetSymbolAddress((void**)&f1h, g_f1h); cudaGetSymbolAddress((void**)&f1l, g_f1l);

    // fused split conversion of all inputs
    pairify_all<<<(SEG0 + 5 * SEGW) / 256, 256>>>(
        (const float4*)O0,   O0h, O0l,
        (const float4*)Ww,   Wwh, Wwl,
        (const float4*)Uw,   Uwh, Uwl,
        (const float4*)Hw,   Hwh, Hwl,
        (const float4*)fc0w, f0h, f0l,
        (const float4*)fc1w, f1h, f1l);

    auto pgrid = [&](int tiles) { return tiles < nsm ? tiles : nsm; };

    // q = O0 @ Ww^T + Wb  [8192, 1024]  (3 sweeps); tiles = 4 x 64 = 256
    {
        int gx = DHID / 256, tiles = gx * (TOK / 128);
        gemm_pair<3, true, false, false, false, true><<<pgrid(tiles), 256, SM_BYTES>>>(
            O0h, O0l, Wwh, Wwl, Wb, nullptr, nullptr, qh, ql, gx, tiles, DHID, DIM);
        gemm_pair<3, true, false, false, false, true><<<pgrid(tiles), 256, SM_BYTES>>>(
            O0h, O0l, Uwh, Uwl, Ub, nullptr, nullptr, kh, kl, gx, tiles, DHID, DIM);
    }
    // vT = Hw @ O0^T + Hb (row-bias) [1024, 8192]; tiles = 32 x 8 = 256
    {
        int gx = TOK / 256, tiles = gx * (DHID / 128);
        gemm_pair<3, false, true, false, false, true><<<pgrid(tiles), 256, SM_BYTES>>>(
            Hwh, Hwl, O0h, O0l, Hb, nullptr, nullptr, vTh, vTl, gx, tiles, TOK, DIM);
    }
    // scores = q @ k^T (fp32 out) [8192, 8192]; tiles = 32 x 64 = 2048
    {
        int gx = TOK / 256, tiles = gx * (TOK / 128);
        gemm_pair<3, false, false, false, true, false><<<pgrid(tiles), 256, SM_BYTES>>>(
            qh, ql, kh, kl, nullptr, nullptr, s, nullptr, nullptr, gx, tiles, TOK, DHID);
    }
    // softmax -> split weights
    softmax_pair<<<TOK, 256>>>(s, Sh, Sl);
    // ctx = Spair @ vT^T [8192, 1024] (2 sweeps); tiles = 4 x 64 (bx fast -> S L2 reuse)
    {
        int gx = DHID / 256, tiles = gx * (TOK / 128);
        gemm_pair<2, false, false, false, false, true><<<pgrid(tiles), 256, SM_BYTES>>>(
            Sh, Sl, vTh, vTl, nullptr, nullptr, nullptr, ch, cl, gx, tiles, DHID, TOK);
    }
    // O1 = O0 + ctx @ fc0w^T + fc0b [8192, 2048] (2 sweeps); tiles = 8 x 64 = 512
    {
        int gx = DIM / 256, tiles = gx * (TOK / 128);
        gemm_pair<2, true, false, true, true, true><<<pgrid(tiles), 256, SM_BYTES>>>(
            ch, cl, f0h, f0l, fc0b, O0, O1, O1h, O1l, gx, tiles, DIM, DHID);
    }
    // O2 = O1 @ fc1w^T + fc1b [8192, 1024] (2 sweeps); tiles = 4 x 64 = 256
    {
        int gx = DOUT / 256, tiles = gx * (TOK / 128);
        gemm_pair<2, true, false, false, true, false><<<pgrid(tiles), 256, SM_BYTES>>>(
            O1h, O1l, f1h, f1l, fc1b, nullptr, O2, nullptr, nullptr, gx, tiles, DOUT, DIM);
    }
}

// round 12
// speedup vs baseline: 1.0417x; 1.0417x over previous
#include <cuda_runtime.h>
#include <cuda_fp16.h>
#include <cstdint>
#include <math.h>

#define TOK 8192
#define DIM 2048
#define DHID 1024
#define DOUT 1024

// ---------------------------------------------------------------------------
// Scratch (__device__ globals; allocation-free per harness rules)
// ---------------------------------------------------------------------------
__device__ __align__(256) float g_s[(size_t)TOK * TOK];             // fp32 scores

__device__ __align__(256) __half g_O0h[(size_t)TOK * DIM];
__device__ __align__(256) __half g_O0l[(size_t)TOK * DIM];
__device__ __align__(256) __half g_Wwh[(size_t)DHID * DIM];
__device__ __align__(256) __half g_Wwl[(size_t)DHID * DIM];
__device__ __align__(256) __half g_Uwh[(size_t)DHID * DIM];
__device__ __align__(256) __half g_Uwl[(size_t)DHID * DIM];
__device__ __align__(256) __half g_Hwh[(size_t)DHID * DIM];
__device__ __align__(256) __half g_Hwl[(size_t)DHID * DIM];
__device__ __align__(256) __half g_qh[(size_t)TOK * DHID];
__device__ __align__(256) __half g_ql[(size_t)TOK * DHID];
__device__ __align__(256) __half g_kh[(size_t)TOK * DHID];
__device__ __align__(256) __half g_kl[(size_t)TOK * DHID];
__device__ __align__(256) __half g_vTh[(size_t)DHID * TOK];
__device__ __align__(256) __half g_vTl[(size_t)DHID * TOK];
__device__ __align__(256) __half g_Sh[(size_t)TOK * TOK];
__device__ __align__(256) __half g_Sl[(size_t)TOK * TOK];
__device__ __align__(256) __half g_ch[(size_t)TOK * DHID];
__device__ __align__(256) __half g_cl[(size_t)TOK * DHID];
__device__ __align__(256) __half g_f0h[(size_t)DIM * DHID];
__device__ __align__(256) __half g_f0l[(size_t)DIM * DHID];
__device__ __align__(256) __half g_O1h[(size_t)TOK * DIM];
__device__ __align__(256) __half g_O1l[(size_t)TOK * DIM];
__device__ __align__(256) __half g_f1h[(size_t)DOUT * DIM];
__device__ __align__(256) __half g_f1l[(size_t)DOUT * DIM];

// ---------------------------------------------------------------------------
// helpers
// ---------------------------------------------------------------------------
__device__ __forceinline__ uint32_t smem_to_u32(const void* p) {
    uint32_t a;
    asm("{ .reg .u64 t; cvta.to.shared.u64 t, %1; cvt.u32.u64 %0, t; }" : "=r"(a) : "l"(p));
    return a;
}
#define SWZ128(o) ((o) ^ (((o) >> 3) & 0x70))

__device__ __forceinline__ void ldmatrix4(uint32_t* r, uint32_t addr) {
    asm volatile("ldmatrix.sync.aligned.m8n8.x4.shared.b16 {%0,%1,%2,%3}, [%4];"
                 : "=r"(r[0]), "=r"(r[1]), "=r"(r[2]), "=r"(r[3]) : "r"(addr));
}
__device__ __forceinline__ void mma16816(float* c, const uint32_t* a, const uint32_t* b) {
    asm volatile("mma.sync.aligned.m16n8k16.row.col.f32.f16.f16.f32 "
                 "{%0,%1,%2,%3}, {%4,%5,%6,%7}, {%8,%9}, {%0,%1,%2,%3};"
                 : "+f"(c[0]), "+f"(c[1]), "+f"(c[2]), "+f"(c[3])
                 : "r"(a[0]), "r"(a[1]), "r"(a[2]), "r"(a[3]), "r"(b[0]), "r"(b[1]));
}
__device__ __forceinline__ void cp_async16(uint32_t dst, const void* src) {
    asm volatile("cp.async.cg.shared.global [%0], [%1], 16;" :: "r"(dst), "l"(src));
}
#define CP_COMMIT()  asm volatile("cp.async.commit_group;" ::: "memory")
#define CP_WAIT1()   asm volatile("cp.async.wait_group 1;" ::: "memory")

__device__ __forceinline__ void pair_store(__half* __restrict__ hi,
                                           __half* __restrict__ lo,
                                           size_t idx, float v) {
    __half h = __float2half_rn(v);
    hi[idx] = h;
    lo[idx] = __float2half_rn(v - __half2float(h));
}

// ---------------------------------------------------------------------------
// GEMM NT: C[M,N] = pair(A)[M,K] * pair(B)[N,K]^T (+bias)(+res)
// CTA tile 128x256, BK=32, SW128 smem [hi 64B | lo 64B] per row.
// 16 warps as 4(m) x 4(n); warp tile 32x64  (acc = 64 regs/thread).
// SWEEPS=3: hi*hi + lo(A)*hi(B) + hi(A)*lo(B);  SWEEPS=2: drops B-lo term.
// 3-stage cp.async pipeline (48KB/stage).
// ---------------------------------------------------------------------------
#define STAGE_BYTES 49152
#define SM_BYTES (3 * STAGE_BYTES)

template<int SWEEPS, bool COLBIAS, bool ROWBIAS, bool RES, bool OUTF, bool OUTP>
__global__ void __launch_bounds__(512, 1)
gemm_pair(const __half* __restrict__ Ahi, const __half* __restrict__ Alo,
          const __half* __restrict__ Bhi, const __half* __restrict__ Blo,
          const float* __restrict__ bias, const float* __restrict__ res,
          float* __restrict__ Cf,
          __half* __restrict__ Chi, __half* __restrict__ Clo,
          int M, int N, int K)
{
    extern __shared__ char smem[];
    const uint32_t smem_base = smem_to_u32(smem);
    const int tid  = threadIdx.x;
    const int wid  = tid >> 5;
    const int lane = tid & 31;
    const int wm   = wid >> 2;        // 0..3  (m 32-row slice)
    const int wn   = wid & 3;         // 0..3  (n 64-col quarter)
    const int bm = blockIdx.y << 7;
    const int bn = blockIdx.x << 8;

    float acc[2][8][4];
    #pragma unroll
    for (int i = 0; i < 2; i++)
        #pragma unroll
        for (int j = 0; j < 8; j++)
            #pragma unroll
            for (int e = 0; e < 4; e++) acc[i][j][e] = 0.0f;

    const int NCH = K >> 5;           // K/32 chunks

    // stage layout: A 128 rows x 128B at +0 (16KB), B 256 rows x 128B at +16KB
    auto load_chunk = [&](int kk, int slot) {
        const uint32_t sbase = smem_base + slot * STAGE_BYTES;
        #pragma unroll
        for (int it = 0; it < 6; it++) {
            int id  = it * 512 + tid;         // 0..3071 16B-chunks
            int isB = id >= 1024;
            int id2 = isB ? id - 1024 : id;
            int row = id2 >> 3;
            int rem = id2 & 7;
            int hl  = rem >> 2;               // 0 = hi, 1 = lo
            int kc  = rem & 3;                // 16B piece within 64B half
            uint32_t cb  = (uint32_t)(hl * 64 + kc * 16);
            uint32_t dst = sbase + (isB ? 16384u : 0u)
                         + SWZ128((uint32_t)(row << 7) + cb);
            const __half* src;
            if (isB) src = (hl ? Blo : Bhi) + (size_t)(bn + row) * K;
            else     src = (hl ? Alo : Ahi) + (size_t)(bm + row) * K;
            cp_async16(dst, src + ((size_t)kk << 5) + kc * 8);
        }
    };

    load_chunk(0, 0); CP_COMMIT();
    load_chunk(1, 1); CP_COMMIT();

    // ldmatrix address components (constant across chunks)
    const int arow0 = (wm << 5) + (lane & 15);          // A m-row within tile
    const uint32_t acol = (uint32_t)((lane >> 4) << 4); // A 16B k-half select
    const int brow0 = (wn << 6) + ((lane >> 4) << 3) + (lane & 7);
    const uint32_t bcol = (uint32_t)(((lane >> 3) & 1) << 4);

    for (int c = 0; c < NCH; c++) {
        CP_WAIT1();
        __syncthreads();
        const uint32_t sbase = smem_base + (c % 3) * STAGE_BYTES;
        const uint32_t Abase = sbase;
        const uint32_t Bbase = sbase + 16384u;

        #pragma unroll
        for (int ks = 0; ks < 2; ks++) {
            const uint32_t kb = (uint32_t)(ks << 5);
            uint32_t Ah[2][4], Ax[2][4], Bf[4][4];
            // hi fragments
            #pragma unroll
            for (int f = 0; f < 2; f++) {
                uint32_t ro = (uint32_t)((arow0 + (f << 4)) << 7);
                ldmatrix4(Ah[f], Abase + SWZ128(ro + kb + acol));
            }
            #pragma unroll
            for (int g = 0; g < 4; g++) {
                uint32_t ro = (uint32_t)((brow0 + (g << 4)) << 7);
                ldmatrix4(Bf[g], Bbase + SWZ128(ro + kb + bcol));
            }
            // hi * hi
            #pragma unroll
            for (int mf = 0; mf < 2; mf++)
                #pragma unroll
                for (int nf = 0; nf < 8; nf++)
                    mma16816(acc[mf][nf], Ah[mf], &Bf[nf >> 1][(nf & 1) << 1]);
            // lo(A) * hi(B)
            #pragma unroll
            for (int f = 0; f < 2; f++) {
                uint32_t ro = (uint32_t)((arow0 + (f << 4)) << 7);
                ldmatrix4(Ax[f], Abase + SWZ128(ro + kb + acol + 64u));
            }
            #pragma unroll
            for (int mf = 0; mf < 2; mf++)
                #pragma unroll
                for (int nf = 0; nf < 8; nf++)
                    mma16816(acc[mf][nf], Ax[mf], &Bf[nf >> 1][(nf & 1) << 1]);
            if (SWEEPS == 3) {
                // hi(A) * lo(B)  (overwrite B frags with lo)
                #pragma unroll
                for (int g = 0; g < 4; g++) {
                    uint32_t ro = (uint32_t)((brow0 + (g << 4)) << 7);
                    ldmatrix4(Bf[g], Bbase + SWZ128(ro + kb + bcol + 64u));
                }
                #pragma unroll
                for (int mf = 0; mf < 2; mf++)
                    #pragma unroll
                    for (int nf = 0; nf < 8; nf++)
                        mma16816(acc[mf][nf], Ah[mf], &Bf[nf >> 1][(nf & 1) << 1]);
            }
        }
        if (c + 2 < NCH) load_chunk(c + 2, (c + 2) % 3);
        CP_COMMIT();
    }

    // ------------------------- epilogue -------------------------
    const int qrow = lane >> 2;           // 0..7
    const int qcol = (lane & 3) << 1;     // 0,2,4,6
    #pragma unroll
    for (int mf = 0; mf < 2; mf++) {
        #pragma unroll
        for (int half = 0; half < 2; half++) {
            const int r = bm + (wm << 5) + (mf << 4) + qrow + (half << 3);
            float rb = 0.0f;
            if (ROWBIAS) rb = bias[r];
            #pragma unroll
            for (int nf = 0; nf < 8; nf++) {
                const int col = bn + (wn << 6) + (nf << 3) + qcol;
                const size_t idx = (size_t)r * N + col;
                float v0 = acc[mf][nf][half * 2 + 0];
                float v1 = acc[mf][nf][half * 2 + 1];
                if (COLBIAS) { v0 += bias[col]; v1 += bias[col + 1]; }
                if (ROWBIAS) { v0 += rb; v1 += rb; }
                if (RES)     { v0 += res[idx]; v1 += res[idx + 1]; }
                if (OUTF)    { *(float2*)(Cf + idx) = make_float2(v0, v1); }
                if (OUTP) {
                    pair_store(Chi, Clo, idx,     v0);
                    pair_store(Chi, Clo, idx + 1, v1);
                }
            }
        }
    }
}

// ---------------------------------------------------------------------------
// Fused fp32 -> (hi, lo) fp16 split conversion for all 6 source arrays
// ---------------------------------------------------------------------------
#define SEG0 4194304
#define SEGW 524288

__global__ void __launch_bounds__(256)
pairify_all(const float4* __restrict__ O0,   __half* __restrict__ O0h,  __half* __restrict__ O0l,
            const float4* __restrict__ Ww,   __half* __restrict__ Wwh,  __half* __restrict__ Wwl,
            const float4* __restrict__ Uw,   __half* __restrict__ Uwh,  __half* __restrict__ Uwl,
            const float4* __restrict__ Hw,   __half* __restrict__ Hwh,  __half* __restrict__ Hwl,
            const float4* __restrict__ f0w,  __half* __restrict__ f0h,  __half* __restrict__ f0l,
            const float4* __restrict__ f1w,  __half* __restrict__ f1h,  __half* __restrict__ f1l)
{
    int i = blockIdx.x * blockDim.x + threadIdx.x;
    const float4* src; __half* hi; __half* lo; int off;
    if (i < SEG0) {
        src = O0; hi = O0h; lo = O0l; off = i;
    } else {
        int j = i - SEG0;
        int seg = j / SEGW;
        off = j - seg * SEGW;
        switch (seg) {
            case 0:  src = Ww;  hi = Wwh; lo = Wwl; break;
            case 1:  src = Uw;  hi = Uwh; lo = Uwl; break;
            case 2:  src = Hw;  hi = Hwh; lo = Hwl; break;
            case 3:  src = f0w; hi = f0h; lo = f0l; break;
            default: src = f1w; hi = f1h; lo = f1l; break;
        }
    }
    float4 v = src[off];
    size_t b = (size_t)off * 4;
    pair_store(hi, lo, b + 0, v.x);
    pair_store(hi, lo, b + 1, v.y);
    pair_store(hi, lo, b + 2, v.z);
    pair_store(hi, lo, b + 3, v.w);
}

// ---------------------------------------------------------------------------
// Row softmax: fp32 scores in, (hi, lo) fp16 split weights out
// ---------------------------------------------------------------------------
__global__ void __launch_bounds__(256)
softmax_pair(const float* __restrict__ S, __half* __restrict__ Wh,
             __half* __restrict__ Wl)
{
    __shared__ float red[8];
    const size_t rowbase = (size_t)blockIdx.x * TOK;
    const float* p = S + rowbase;
    const int tid = threadIdx.x;
    const int lane = tid & 31;
    const int warp = tid >> 5;

    float4 vals[8];
    float lmax = -INFINITY;
    #pragma unroll
    for (int i = 0; i < 8; i++) {
        vals[i] = *(const float4*)(p + ((i << 8) + tid) * 4);
        lmax = fmaxf(lmax, fmaxf(fmaxf(vals[i].x, vals[i].y), fmaxf(vals[i].z, vals[i].w)));
    }
    #pragma unroll
    for (int o = 16; o > 0; o >>= 1)
        lmax = fmaxf(lmax, __shfl_xor_sync(0xffffffffu, lmax, o));
    if (lane == 0) red[warp] = lmax;
    __syncthreads();
    float rmax = red[0];
    #pragma unroll
    for (int w = 1; w < 8; w++) rmax = fmaxf(rmax, red[w]);
    __syncthreads();

    float lsum = 0.0f;
    #pragma unroll
    for (int i = 0; i < 8; i++) {
        vals[i].x = expf(vals[i].x - rmax);
        vals[i].y = expf(vals[i].y - rmax);
        vals[i].z = expf(vals[i].z - rmax);
        vals[i].w = expf(vals[i].w - rmax);
        lsum += (vals[i].x + vals[i].y) + (vals[i].z + vals[i].w);
    }
    #pragma unroll
    for (int o = 16; o > 0; o >>= 1)
        lsum += __shfl_xor_sync(0xffffffffu, lsum, o);
    if (lane == 0) red[warp] = lsum;
    __syncthreads();
    float rsum = 0.0f;
    #pragma unroll
    for (int w = 0; w < 8; w++) rsum += red[w];
    const float inv = 1.0f / rsum;

    #pragma unroll
    for (int i = 0; i < 8; i++) {
        const size_t b = rowbase + ((i << 8) + tid) * 4;
        pair_store(Wh, Wl, b + 0, vals[i].x * inv);
        pair_store(Wh, Wl, b + 1, vals[i].y * inv);
        pair_store(Wh, Wl, b + 2, vals[i].z * inv);
        pair_store(Wh, Wl, b + 3, vals[i].w * inv);
    }
}

// ---------------------------------------------------------------------------
// Launch
// ---------------------------------------------------------------------------
template<int SW, bool CB, bool RB, bool RE, bool OF, bool OP>
static void set_smem_attr() {
    cudaFuncSetAttribute(gemm_pair<SW, CB, RB, RE, OF, OP>,
                         cudaFuncAttributeMaxDynamicSharedMemorySize, SM_BYTES);
}

extern "C" void kernel_launch(void* const* d_in, const int* in_sizes, int n_in,
                              void* d_out, int out_size)
{
    const float* O0   = (const float*)d_in[0];
    const float* Ww   = (const float*)d_in[1];
    const float* Wb   = (const float*)d_in[2];
    const float* Uw   = (const float*)d_in[3];
    const float* Ub   = (const float*)d_in[4];
    const float* Hw   = (const float*)d_in[5];
    const float* Hb   = (const float*)d_in[6];
    const float* fc0w = (const float*)d_in[7];
    const float* fc0b = (const float*)d_in[8];
    const float* fc1w = (const float*)d_in[9];
    const float* fc1b = (const float*)d_in[10];

    float* O1 = (float*)d_out;
    float* O2 = O1 + (size_t)TOK * DIM;

    set_smem_attr<3, true,  false, false, false, true >();  // q, k
    set_smem_attr<3, false, true,  false, false, true >();  // vT
    set_smem_attr<3, false, false, false, true,  false>();  // scores
    set_smem_attr<2, false, false, false, false, true >();  // ctx
    set_smem_attr<2, true,  false, true,  true,  true >();  // fc0
    set_smem_attr<2, true,  false, false, true,  false>();  // fc1

    float* s;
    __half *O0h, *O0l, *Wwh, *Wwl, *Uwh, *Uwl, *Hwh, *Hwl;
    __half *qh, *ql, *kh, *kl, *vTh, *vTl, *Sh, *Sl, *ch, *cl;
    __half *f0h, *f0l, *O1h, *O1l, *f1h, *f1l;
    cudaGetSymbolAddress((void**)&s,   g_s);
    cudaGetSymbolAddress((void**)&O0h, g_O0h); cudaGetSymbolAddress((void**)&O0l, g_O0l);
    cudaGetSymbolAddress((void**)&Wwh, g_Wwh); cudaGetSymbolAddress((void**)&Wwl, g_Wwl);
    cudaGetSymbolAddress((void**)&Uwh, g_Uwh); cudaGetSymbolAddress((void**)&Uwl, g_Uwl);
    cudaGetSymbolAddress((void**)&Hwh, g_Hwh); cudaGetSymbolAddress((void**)&Hwl, g_Hwl);
    cudaGetSymbolAddress((void**)&qh,  g_qh);  cudaGetSymbolAddress((void**)&ql,  g_ql);
    cudaGetSymbolAddress((void**)&kh,  g_kh);  cudaGetSymbolAddress((void**)&kl,  g_kl);
    cudaGetSymbolAddress((void**)&vTh, g_vTh); cudaGetSymbolAddress((void**)&vTl, g_vTl);
    cudaGetSymbolAddress((void**)&Sh,  g_Sh);  cudaGetSymbolAddress((void**)&Sl,  g_Sl);
    cudaGetSymbolAddress((void**)&ch,  g_ch);  cudaGetSymbolAddress((void**)&cl,  g_cl);
    cudaGetSymbolAddress((void**)&f0h, g_f0h); cudaGetSymbolAddress((void**)&f0l, g_f0l);
    cudaGetSymbolAddress((void**)&O1h, g_O1h); cudaGetSymbolAddress((void**)&O1l, g_O1l);
    cudaGetSymbolAddress((void**)&f1h, g_f1h); cudaGetSymbolAddress((void**)&f1l, g_f1l);

    // fused split conversion of all inputs
    pairify_all<<<(SEG0 + 5 * SEGW) / 256, 256>>>(
        (const float4*)O0,   O0h, O0l,
        (const float4*)Ww,   Wwh, Wwl,
        (const float4*)Uw,   Uwh, Uwl,
        (const float4*)Hw,   Hwh, Hwl,
        (const float4*)fc0w, f0h, f0l,
        (const float4*)fc1w, f1h, f1l);

    // q = O0 @ Ww^T + Wb           [8192, 1024]   (3 sweeps)
    gemm_pair<3, true, false, false, false, true><<<dim3(DHID / 256, TOK / 128), 512, SM_BYTES>>>(
        O0h, O0l, Wwh, Wwl, Wb, nullptr, nullptr, qh, ql, TOK, DHID, DIM);
    // k = O0 @ Uw^T + Ub           (3 sweeps)
    gemm_pair<3, true, false, false, false, true><<<dim3(DHID / 256, TOK / 128), 512, SM_BYTES>>>(
        O0h, O0l, Uwh, Uwl, Ub, nullptr, nullptr, kh, kl, TOK, DHID, DIM);
    // vT = Hw @ O0^T + Hb (row-bias)  [1024, 8192]  (3 sweeps)
    gemm_pair<3, false, true, false, false, true><<<dim3(TOK / 256, DHID / 128), 512, SM_BYTES>>>(
        Hwh, Hwl, O0h, O0l, Hb, nullptr, nullptr, vTh, vTl, DHID, TOK, DIM);
    // scores = q @ k^T (fp32 out)   [8192, 8192]   (3 sweeps)
    gemm_pair<3, false, false, false, true, false><<<dim3(TOK / 256, TOK / 128), 512, SM_BYTES>>>(
        qh, ql, kh, kl, nullptr, nullptr, s, nullptr, nullptr, TOK, TOK, DHID);
    // softmax -> split weights
    softmax_pair<<<TOK, 256>>>(s, Sh, Sl);
    // ctx = softmax @ v = Spair @ vT^T   [8192, 1024]   (2 sweeps)
    gemm_pair<2, false, false, false, false, true><<<dim3(DHID / 256, TOK / 128), 512, SM_BYTES>>>(
        Sh, Sl, vTh, vTl, nullptr, nullptr, nullptr, ch, cl, TOK, DHID, TOK);
    // O1 = O0 + ctx @ fc0w^T + fc0b  (fp32 + pair out)  [8192, 2048]  (2 sweeps)
    gemm_pair<2, true, false, true, true, true><<<dim3(DIM / 256, TOK / 128), 512, SM_BYTES>>>(
        ch, cl, f0h, f0l, fc0b, O0, O1, O1h, O1l, TOK, DIM, DHID);
    // O2 = O1 @ fc1w^T + fc1b  (fp32 out)  [8192, 1024]  (2 sweeps)
    gemm_pair<2, true, false, false, true, false><<<dim3(DOUT / 256, TOK / 128), 512, SM_BYTES>>>(
        O1h, O1l, f1h, f1l, fc1b, nullptr, O2, nullptr, nullptr, TOK, DOUT, DIM);
}

// round 15
// speedup vs baseline: 1.0802x; 1.0370x over previous
#include <cuda_runtime.h>
#include <cuda_fp16.h>
#include <cstdint>
#include <math.h>

#define TOK 8192
#define DIM 2048
#define DHID 1024
#define DOUT 1024

// ---------------------------------------------------------------------------
// Scratch (__device__ globals; allocation-free per harness rules)
// ---------------------------------------------------------------------------
__device__ __align__(256) float g_s[(size_t)TOK * TOK];             // fp32 scores

__device__ __align__(256) __half g_O0h[(size_t)TOK * DIM];
__device__ __align__(256) __half g_O0l[(size_t)TOK * DIM];
// W and U concatenated: rows 0..1023 = Ww, rows 1024..2047 = Uw  (row-major, K=2048)
__device__ __align__(256) __half g_WUh[(size_t)(2 * DHID) * DIM];
__device__ __align__(256) __half g_WUl[(size_t)(2 * DHID) * DIM];
__device__ __align__(256) float  g_qkb[2 * DHID];                   // Wb ++ Ub
__device__ __align__(256) __half g_Hwh[(size_t)DHID * DIM];
__device__ __align__(256) __half g_Hwl[(size_t)DHID * DIM];
// fused q||k output: [TOK, 2048], cols 0..1023 = q, 1024..2047 = k
__device__ __align__(256) __half g_qkh[(size_t)TOK * (2 * DHID)];
__device__ __align__(256) __half g_qkl[(size_t)TOK * (2 * DHID)];
__device__ __align__(256) __half g_vTh[(size_t)DHID * TOK];
__device__ __align__(256) __half g_vTl[(size_t)DHID * TOK];
__device__ __align__(256) __half g_Sh[(size_t)TOK * TOK];
__device__ __align__(256) __half g_Sl[(size_t)TOK * TOK];
__device__ __align__(256) __half g_ch[(size_t)TOK * DHID];
__device__ __align__(256) __half g_cl[(size_t)TOK * DHID];
__device__ __align__(256) __half g_f0h[(size_t)DIM * DHID];
__device__ __align__(256) __half g_f0l[(size_t)DIM * DHID];
__device__ __align__(256) __half g_O1h[(size_t)TOK * DIM];
__device__ __align__(256) __half g_O1l[(size_t)TOK * DIM];
__device__ __align__(256) __half g_f1h[(size_t)DOUT * DIM];
__device__ __align__(256) __half g_f1l[(size_t)DOUT * DIM];

// ---------------------------------------------------------------------------
// helpers
// ---------------------------------------------------------------------------
__device__ __forceinline__ uint32_t smem_to_u32(const void* p) {
    uint32_t a;
    asm("{ .reg .u64 t; cvta.to.shared.u64 t, %1; cvt.u32.u64 %0, t; }" : "=r"(a) : "l"(p));
    return a;
}
#define SWZ128(o) ((o) ^ (((o) >> 3) & 0x70))

__device__ __forceinline__ void ldmatrix4(uint32_t* r, uint32_t addr) {
    asm volatile("ldmatrix.sync.aligned.m8n8.x4.shared.b16 {%0,%1,%2,%3}, [%4];"
                 : "=r"(r[0]), "=r"(r[1]), "=r"(r[2]), "=r"(r[3]) : "r"(addr));
}
__device__ __forceinline__ void mma16816(float* c, const uint32_t* a, const uint32_t* b) {
    asm volatile("mma.sync.aligned.m16n8k16.row.col.f32.f16.f16.f32 "
                 "{%0,%1,%2,%3}, {%4,%5,%6,%7}, {%8,%9}, {%0,%1,%2,%3};"
                 : "+f"(c[0]), "+f"(c[1]), "+f"(c[2]), "+f"(c[3])
                 : "r"(a[0]), "r"(a[1]), "r"(a[2]), "r"(a[3]), "r"(b[0]), "r"(b[1]));
}
__device__ __forceinline__ void cp_async16(uint32_t dst, const void* src) {
    asm volatile("cp.async.cg.shared.global [%0], [%1], 16;" :: "r"(dst), "l"(src));
}
#define CP_COMMIT()  asm volatile("cp.async.commit_group;" ::: "memory")
#define CP_WAIT2()   asm volatile("cp.async.wait_group 2;" ::: "memory")

__device__ __forceinline__ void pair_store(__half* __restrict__ hi,
                                           __half* __restrict__ lo,
                                           size_t idx, float v) {
    __half h = __float2half_rn(v);
    hi[idx] = h;
    lo[idx] = __float2half_rn(v - __half2float(h));
}

// ---------------------------------------------------------------------------
// GEMM NT: C[M,N] = pair(A)[M,K] * pair(B)[N,K]^T (+bias)(+res)
// CTA tile 128x256, BK=32, SW128 smem [hi 64B | lo 64B] per row.
// 8 warps as 2(m) x 4(n); warp tile 64x64.
// All 16 ldmatrix issued up-front per k-step, then 32/48 back-to-back MMAs.
// SWEEPS=3: hi*hi + lo(A)*hi(B) + hi(A)*lo(B);  SWEEPS=2: drops B-lo term.
// 4-stage cp.async pipeline (48KB/stage, prefetch distance 3).
// lda/ldb decouple row stride from K (for fused q||k buffers).
// ---------------------------------------------------------------------------
#define STAGE_BYTES 49152
#define SM_BYTES (4 * STAGE_BYTES)

template<int SWEEPS, bool COLBIAS, bool ROWBIAS, bool RES, bool OUTF, bool OUTP>
__global__ void __launch_bounds__(256, 1)
gemm_pair(const __half* __restrict__ Ahi, const __half* __restrict__ Alo,
          const __half* __restrict__ Bhi, const __half* __restrict__ Blo,
          const float* __restrict__ bias, const float* __restrict__ res,
          float* __restrict__ Cf,
          __half* __restrict__ Chi, __half* __restrict__ Clo,
          int M, int N, int K, int lda, int ldb)
{
    extern __shared__ char smem[];
    const uint32_t smem_base = smem_to_u32(smem);
    const int tid  = threadIdx.x;
    const int wid  = tid >> 5;
    const int lane = tid & 31;
    const int wm   = wid >> 2;        // 0..1  (m 64-row half)
    const int wn   = wid & 3;         // 0..3  (n 64-col quarter)
    const int bm = blockIdx.y << 7;
    const int bn = blockIdx.x << 8;

    float acc[4][8][4];
    #pragma unroll
    for (int i = 0; i < 4; i++)
        #pragma unroll
        for (int j = 0; j < 8; j++)
            #pragma unroll
            for (int e = 0; e < 4; e++) acc[i][j][e] = 0.0f;

    const int NCH = K >> 5;           // K/32 chunks

    // stage layout: A 128 rows x 128B at +0 (16KB), B 256 rows x 128B at +16KB
    auto load_chunk = [&](int kk, int slot) {
        const uint32_t sbase = smem_base + slot * STAGE_BYTES;
        #pragma unroll
        for (int it = 0; it < 12; it++) {
            int id  = it * 256 + tid;         // 0..3071 16B-chunks
            int isB = id >= 1024;
            int id2 = isB ? id - 1024 : id;
            int row = id2 >> 3;
            int rem = id2 & 7;
            int hl  = rem >> 2;               // 0 = hi, 1 = lo
            int kc  = rem & 3;                // 16B piece within 64B half
            uint32_t cb  = (uint32_t)(hl * 64 + kc * 16);
            uint32_t dst = sbase + (isB ? 16384u : 0u)
                         + SWZ128((uint32_t)(row << 7) + cb);
            const __half* src;
            if (isB) src = (hl ? Blo : Bhi) + (size_t)(bn + row) * ldb;
            else     src = (hl ? Alo : Ahi) + (size_t)(bm + row) * lda;
            cp_async16(dst, src + ((size_t)kk << 5) + kc * 8);
        }
    };

    load_chunk(0, 0); CP_COMMIT();
    load_chunk(1, 1); CP_COMMIT();
    load_chunk(2, 2); CP_COMMIT();

    // ldmatrix address components (constant across chunks)
    const int arow0 = (wm << 6) + (lane & 15);          // A m-row within tile
    const uint32_t acol = (uint32_t)((lane >> 4) << 4); // A 16B k-half select
    const int brow0 = (wn << 6) + ((lane >> 4) << 3) + (lane & 7);
    const uint32_t bcol = (uint32_t)(((lane >> 3) & 1) << 4);

    for (int c = 0; c < NCH; c++) {
        CP_WAIT2();
        __syncthreads();
        const uint32_t sbase = smem_base + (c & 3) * STAGE_BYTES;
        const uint32_t Abase = sbase;
        const uint32_t Bbase = sbase + 16384u;

        #pragma unroll
        for (int ks = 0; ks < 2; ks++) {
            const uint32_t kb = (uint32_t)(ks << 5);
            uint32_t Ah[4][4], Ax[4][4], Bh[4][4], Bl[4][4];
            // ---- issue ALL fragment loads first (16 LDSM in flight) ----
            #pragma unroll
            for (int f = 0; f < 4; f++) {
                uint32_t ro = (uint32_t)((arow0 + (f << 4)) << 7);
                ldmatrix4(Ah[f], Abase + SWZ128(ro + kb + acol));
            }
            #pragma unroll
            for (int g = 0; g < 4; g++) {
                uint32_t ro = (uint32_t)((brow0 + (g << 4)) << 7);
                ldmatrix4(Bh[g], Bbase + SWZ128(ro + kb + bcol));
            }
            #pragma unroll
            for (int f = 0; f < 4; f++) {
                uint32_t ro = (uint32_t)((arow0 + (f << 4)) << 7);
                ldmatrix4(Ax[f], Abase + SWZ128(ro + kb + acol + 64u));
            }
            if (SWEEPS == 3) {
                #pragma unroll
                for (int g = 0; g < 4; g++) {
                    uint32_t ro = (uint32_t)((brow0 + (g << 4)) << 7);
                    ldmatrix4(Bl[g], Bbase + SWZ128(ro + kb + bcol + 64u));
                }
            }
            // ---- MMA bursts ----
            #pragma unroll
            for (int mf = 0; mf < 4; mf++)
                #pragma unroll
                for (int nf = 0; nf < 8; nf++)
                    mma16816(acc[mf][nf], Ah[mf], &Bh[nf >> 1][(nf & 1) << 1]);
            #pragma unroll
            for (int mf = 0; mf < 4; mf++)
                #pragma unroll
                for (int nf = 0; nf < 8; nf++)
                    mma16816(acc[mf][nf], Ax[mf], &Bh[nf >> 1][(nf & 1) << 1]);
            if (SWEEPS == 3) {
                #pragma unroll
                for (int mf = 0; mf < 4; mf++)
                    #pragma unroll
                    for (int nf = 0; nf < 8; nf++)
                        mma16816(acc[mf][nf], Ah[mf], &Bl[nf >> 1][(nf & 1) << 1]);
            }
        }
        if (c + 3 < NCH) load_chunk(c + 3, (c + 3) & 3);
        CP_COMMIT();
    }

    // ------------------------- epilogue -------------------------
    const int qrow = lane >> 2;           // 0..7
    const int qcol = (lane & 3) << 1;     // 0,2,4,6
    #pragma unroll
    for (int mf = 0; mf < 4; mf++) {
        #pragma unroll
        for (int half = 0; half < 2; half++) {
            const int r = bm + (wm << 6) + (mf << 4) + qrow + (half << 3);
            float rb = 0.0f;
            if (ROWBIAS) rb = bias[r];
            #pragma unroll
            for (int nf = 0; nf < 8; nf++) {
                const int col = bn + (wn << 6) + (nf << 3) + qcol;
                const size_t idx = (size_t)r * N + col;
                float v0 = acc[mf][nf][half * 2 + 0];
                float v1 = acc[mf][nf][half * 2 + 1];
                if (COLBIAS) { v0 += bias[col]; v1 += bias[col + 1]; }
                if (ROWBIAS) { v0 += rb; v1 += rb; }
                if (RES)     { v0 += res[idx]; v1 += res[idx + 1]; }
                if (OUTF)    { *(float2*)(Cf + idx) = make_float2(v0, v1); }
                if (OUTP) {
                    pair_store(Chi, Clo, idx,     v0);
                    pair_store(Chi, Clo, idx + 1, v1);
                }
            }
        }
    }
}

// ---------------------------------------------------------------------------
// Fused fp32 -> (hi, lo) fp16 split conversion for all 6 source arrays
// Ww/Uw land in the concatenated WU buffer (rows 0..1023 / 1024..2047).
// ---------------------------------------------------------------------------
#define SEG0 4194304
#define SEGW 524288

__global__ void __launch_bounds__(256)
pairify_all(const float4* __restrict__ O0,   __half* __restrict__ O0h,  __half* __restrict__ O0l,
            const float4* __restrict__ Ww,
            const float4* __restrict__ Uw,   __half* __restrict__ WUh,  __half* __restrict__ WUl,
            const float4* __restrict__ Hw,   __half* __restrict__ Hwh,  __half* __restrict__ Hwl,
            const float4* __restrict__ f0w,  __half* __restrict__ f0h,  __half* __restrict__ f0l,
            const float4* __restrict__ f1w,  __half* __restrict__ f1h,  __half* __restrict__ f1l)
{
    int i = blockIdx.x * blockDim.x + threadIdx.x;
    const float4* src; __half* hi; __half* lo; int off;
    if (i < SEG0) {
        src = O0; hi = O0h; lo = O0l; off = i;
    } else {
        int j = i - SEG0;
        int seg = j / SEGW;
        off = j - seg * SEGW;
        switch (seg) {
            case 0:  src = Ww;  hi = WUh;                         lo = WUl;                         break;
            case 1:  src = Uw;  hi = WUh + (size_t)DHID * DIM;    lo = WUl + (size_t)DHID * DIM;    break;
            case 2:  src = Hw;  hi = Hwh;                         lo = Hwl;                         break;
            case 3:  src = f0w; hi = f0h;                         lo = f0l;                         break;
            default: src = f1w; hi = f1h;                         lo = f1l;                         break;
        }
    }
    float4 v = src[off];
    size_t b = (size_t)off * 4;
    pair_store(hi, lo, b + 0, v.x);
    pair_store(hi, lo, b + 1, v.y);
    pair_store(hi, lo, b + 2, v.z);
    pair_store(hi, lo, b + 3, v.w);
}

__global__ void __launch_bounds__(1024)
concat_bias(const float* __restrict__ Wb, const float* __restrict__ Ub,
            float* __restrict__ qkb)
{
    int i = blockIdx.x * 1024 + threadIdx.x;
    qkb[i] = (i < DHID) ? Wb[i] : Ub[i - DHID];
}

// ---------------------------------------------------------------------------
// Row softmax: fp32 scores in, (hi, lo) fp16 split weights out
// ---------------------------------------------------------------------------
__global__ void __launch_bounds__(256)
softmax_pair(const float* __restrict__ S, __half* __restrict__ Wh,
             __half* __restrict__ Wl)
{
    __shared__ float red[8];
    const size_t rowbase = (size_t)blockIdx.x * TOK;
    const float* p = S + rowbase;
    const int tid = threadIdx.x;
    const int lane = tid & 31;
    const int warp = tid >> 5;

    float4 vals[8];
    float lmax = -INFINITY;
    #pragma unroll
    for (int i = 0; i < 8; i++) {
        vals[i] = *(const float4*)(p + ((i << 8) + tid) * 4);
        lmax = fmaxf(lmax, fmaxf(fmaxf(vals[i].x, vals[i].y), fmaxf(vals[i].z, vals[i].w)));
    }
    #pragma unroll
    for (int o = 16; o > 0; o >>= 1)
        lmax = fmaxf(lmax, __shfl_xor_sync(0xffffffffu, lmax, o));
    if (lane == 0) red[warp] = lmax;
    __syncthreads();
    float rmax = red[0];
    #pragma unroll
    for (int w = 1; w < 8; w++) rmax = fmaxf(rmax, red[w]);
    __syncthreads();

    float lsum = 0.0f;
    #pragma unroll
    for (int i = 0; i < 8; i++) {
        vals[i].x = expf(vals[i].x - rmax);
        vals[i].y = expf(vals[i].y - rmax);
        vals[i].z = expf(vals[i].z - rmax);
        vals[i].w = expf(vals[i].w - rmax);
        lsum += (vals[i].x + vals[i].y) + (vals[i].z + vals[i].w);
    }
    #pragma unroll
    for (int o = 16; o > 0; o >>= 1)
        lsum += __shfl_xor_sync(0xffffffffu, lsum, o);
    if (lane == 0) red[warp] = lsum;
    __syncthreads();
    float rsum = 0.0f;
    #pragma unroll
    for (int w = 0; w < 8; w++) rsum += red[w];
    const float inv = 1.0f / rsum;

    #pragma unroll
    for (int i = 0; i < 8; i++) {
        const size_t b = rowbase + ((i << 8) + tid) * 4;
        pair_store(Wh, Wl, b + 0, vals[i].x * inv);
        pair_store(Wh, Wl, b + 1, vals[i].y * inv);
        pair_store(Wh, Wl, b + 2, vals[i].z * inv);
        pair_store(Wh, Wl, b + 3, vals[i].w * inv);
    }
}

// ---------------------------------------------------------------------------
// Launch
// ---------------------------------------------------------------------------
template<int SW, bool CB, bool RB, bool RE, bool OF, bool OP>
static void set_smem_attr() {
    cudaFuncSetAttribute(gemm_pair<SW, CB, RB, RE, OF, OP>,
                         cudaFuncAttributeMaxDynamicSharedMemorySize, SM_BYTES);
}

extern "C" void kernel_launch(void* const* d_in, const int* in_sizes, int n_in,
                              void* d_out, int out_size)
{
    const float* O0   = (const float*)d_in[0];
    const float* Ww   = (const float*)d_in[1];
    const float* Wb   = (const float*)d_in[2];
    const float* Uw   = (const float*)d_in[3];
    const float* Ub   = (const float*)d_in[4];
    const float* Hw   = (const float*)d_in[5];
    const float* Hb   = (const float*)d_in[6];
    const float* fc0w = (const float*)d_in[7];
    const float* fc0b = (const float*)d_in[8];
    const float* fc1w = (const float*)d_in[9];
    const float* fc1b = (const float*)d_in[10];

    float* O1 = (float*)d_out;
    float* O2 = O1 + (size_t)TOK * DIM;

    set_smem_attr<3, true,  false, false, false, true >();  // qk fused
    set_smem_attr<3, false, true,  false, false, true >();  // vT
    set_smem_attr<3, false, false, false, true,  false>();  // scores
    set_smem_attr<2, false, false, false, false, true >();  // ctx
    set_smem_attr<2, true,  false, true,  true,  true >();  // fc0
    set_smem_attr<2, true,  false, false, true,  false>();  // fc1

    float *s, *qkb;
    __half *O0h, *O0l, *WUh, *WUl, *Hwh, *Hwl;
    __half *qkh, *qkl, *vTh, *vTl, *Sh, *Sl, *ch, *cl;
    __half *f0h, *f0l, *O1h, *O1l, *f1h, *f1l;
    cudaGetSymbolAddress((void**)&s,   g_s);
    cudaGetSymbolAddress((void**)&qkb, g_qkb);
    cudaGetSymbolAddress((void**)&O0h, g_O0h); cudaGetSymbolAddress((void**)&O0l, g_O0l);
    cudaGetSymbolAddress((void**)&WUh, g_WUh); cudaGetSymbolAddress((void**)&WUl, g_WUl);
    cudaGetSymbolAddress((void**)&Hwh, g_Hwh); cudaGetSymbolAddress((void**)&Hwl, g_Hwl);
    cudaGetSymbolAddress((void**)&qkh, g_qkh); cudaGetSymbolAddress((void**)&qkl, g_qkl);
    cudaGetSymbolAddress((void**)&vTh, g_vTh); cudaGetSymbolAddress((void**)&vTl, g_vTl);
    cudaGetSymbolAddress((void**)&Sh,  g_Sh);  cudaGetSymbolAddress((void**)&Sl,  g_Sl);
    cudaGetSymbolAddress((void**)&ch,  g_ch);  cudaGetSymbolAddress((void**)&cl,  g_cl);
    cudaGetSymbolAddress((void**)&f0h, g_f0h); cudaGetSymbolAddress((void**)&f0l, g_f0l);
    cudaGetSymbolAddress((void**)&O1h, g_O1h); cudaGetSymbolAddress((void**)&O1l, g_O1l);
    cudaGetSymbolAddress((void**)&f1h, g_f1h); cudaGetSymbolAddress((void**)&f1l, g_f1l);

    // fused split conversion + bias concat
    pairify_all<<<(SEG0 + 5 * SEGW) / 256, 256>>>(
        (const float4*)O0,   O0h, O0l,
        (const float4*)Ww,
        (const float4*)Uw,   WUh, WUl,
        (const float4*)Hw,   Hwh, Hwl,
        (const float4*)fc0w, f0h, f0l,
        (const float4*)fc1w, f1h, f1l);
    concat_bias<<<2, 1024>>>(Wb, Ub, qkb);

    // q||k = O0 @ [Ww;Uw]^T + [Wb;Ub]   [8192, 2048]  (3 sweeps)
    gemm_pair<3, true, false, false, false, true><<<dim3(2 * DHID / 256, TOK / 128), 256, SM_BYTES>>>(
        O0h, O0l, WUh, WUl, qkb, nullptr, nullptr, qkh, qkl,
        TOK, 2 * DHID, DIM, DIM, DIM);
    // vT = Hw @ O0^T + Hb (row-bias)  [1024, 8192]  (3 sweeps)
    gemm_pair<3, false, true, false, false, true><<<dim3(TOK / 256, DHID / 128), 256, SM_BYTES>>>(
        Hwh, Hwl, O0h, O0l, Hb, nullptr, nullptr, vTh, vTl,
        DHID, TOK, DIM, DIM, DIM);
    // scores = q @ k^T (fp32 out)  [8192, 8192]  (3 sweeps)
    // A = qk cols 0..1023 (lda 2048); B = qk cols 1024..2047 (ldb 2048)
    gemm_pair<3, false, false, false, true, false><<<dim3(TOK / 256, TOK / 128), 256, SM_BYTES>>>(
        qkh, qkl, qkh + DHID, qkl + DHID, nullptr, nullptr, s, nullptr, nullptr,
        TOK, TOK, DHID, 2 * DHID, 2 * DHID);
    // softmax -> split weights
    softmax_pair<<<TOK, 256>>>(s, Sh, Sl);
    // ctx = Spair @ vT^T  [8192, 1024]  (2 sweeps)
    gemm_pair<2, false, false, false, false, true><<<dim3(DHID / 256, TOK / 128), 256, SM_BYTES>>>(
        Sh, Sl, vTh, vTl, nullptr, nullptr, nullptr, ch, cl,
        TOK, DHID, TOK, TOK, TOK);
    // O1 = O0 + ctx @ fc0w^T + fc0b  (fp32 + pair out)  [8192, 2048]  (2 sweeps)
    gemm_pair<2, true, false, true, true, true><<<dim3(DIM / 256, TOK / 128), 256, SM_BYTES>>>(
        ch, cl, f0h, f0l, fc0b, O0, O1, O1h, O1l,
        TOK, DIM, DHID, DHID, DHID);
    // O2 = O1 @ fc1w^T + fc1b  (fp32 out)  [8192, 1024]  (2 sweeps)
    gemm_pair<2, true, false, false, true, false><<<dim3(DOUT / 256, TOK / 128), 256, SM_BYTES>>>(
        O1h, O1l, f1h, f1l, fc1b, nullptr, O2, nullptr, nullptr,
        TOK, DOUT, DIM, DIM, DIM);
}